// round 3
// baseline (speedup 1.0000x reference)
#include <cuda_runtime.h>
#include <math.h>

// ---------------------------------------------------------------------------
// Problem constants
// ---------------------------------------------------------------------------
static const int Bc   = 32;      // batch
static const int Nc   = 3136;    // tokens
static const int Cc   = 384;     // channels
static const int Hc   = 8;       // heads
static const int HDc  = 48;      // head dim
static const int NTc  = 196;     // query tokens
static const int C2c  = 768;     // 2*C
static const float SCALE = 0.14433756729740643f; // 1/sqrt(48)

// ---------------------------------------------------------------------------
// Device scratch (static allocations only — no cudaMalloc allowed)
// ---------------------------------------------------------------------------
__device__ float g_mu   [Bc * Nc];
__device__ float g_rstd [Bc * Nc];
__device__ float g_kv   [(size_t)Bc * Nc * C2c];      // 308 MB: k cols 0..383, v cols 384..767
__device__ float g_kvsub[Bc * NTc * C2c];             // gathered rows at idx_sub
__device__ float g_kidx [Bc * NTc * Cc];              // gathered k rows at idxs
__device__ float g_S    [Bc * Hc * NTc * NTc];        // scores scratch (reused for attn1 & attn2)
__device__ float g_q1   [Bc * NTc * Cc];              // q_cond after attn1
__device__ float g_h    [Bc * NTc * C2c];             // MLP hidden
__device__ float g_q2   [Bc * NTc * Cc];              // q_cond after MLP
__device__ int   g_cent [Bc * NTc];                   // centroid token index (in [0,N))
__device__ float g_att  [Bc * NTc * Cc];              // stage-3 attention output

// ---------------------------------------------------------------------------
// f32x2 helpers (Blackwell packed FFMA2: 2x fp32 FMA throughput)
// ---------------------------------------------------------------------------
__device__ __forceinline__ unsigned long long pk2(float x) {
    unsigned long long r;
    unsigned int u = __float_as_uint(x);
    asm("mov.b64 %0, {%1, %1};" : "=l"(r) : "r"(u));
    return r;
}
__device__ __forceinline__ void fma2(unsigned long long& d,
                                     unsigned long long a,
                                     unsigned long long b) {
    asm("fma.rn.f32x2 %0, %1, %2, %3;" : "=l"(d) : "l"(a), "l"(b), "l"(d));
}
__device__ __forceinline__ float2 unpk(unsigned long long v) {
    unsigned int lo, hi;
    asm("mov.b64 {%0, %1}, %2;" : "=r"(lo), "=r"(hi) : "l"(v));
    return make_float2(__uint_as_float(lo), __uint_as_float(hi));
}

// ---------------------------------------------------------------------------
// Kernel: LayerNorm statistics (mean, rstd) per row of x
// ---------------------------------------------------------------------------
__global__ void ln_stats_k(const float* __restrict__ x) {
    int row  = blockIdx.x * 4 + (threadIdx.x >> 5);
    int lane = threadIdx.x & 31;
    if (row >= Bc * Nc) return;
    const float* xr = x + (size_t)row * Cc;
    float s = 0.f, s2 = 0.f;
#pragma unroll
    for (int j = 0; j < 12; j++) {
        float v = __ldg(xr + lane + 32 * j);
        s += v; s2 += v * v;
    }
#pragma unroll
    for (int o = 16; o; o >>= 1) {
        s  += __shfl_xor_sync(0xffffffffu, s,  o);
        s2 += __shfl_xor_sync(0xffffffffu, s2, o);
    }
    if (lane == 0) {
        float m   = s * (1.0f / 384.0f);
        float var = s2 * (1.0f / 384.0f) - m * m;
        g_mu[row]   = m;
        g_rstd[row] = rsqrtf(var + 1e-6f);
    }
}

// ---------------------------------------------------------------------------
// Generic tiled GEMM:  C[m,n] = act( alpha * sum_k A[m,k]*B[n,k] + bias[n] )
// A optionally layer-normalized on load. Batched over blockIdx.z = b*Hh + h.
// BM=BN=64, BK=16, 256 threads, 4x4 per thread via f32x2 pairs.
// ---------------------------------------------------------------------------
struct GP {
    const float* A; const float* Bm; float* Cm;
    const float* bias;
    const float* mu; const float* rstd; const float* lnw; const float* lnb;
    long sAm, sAk, sBn, sBk, sCm, sCn;
    long strAb, strAh, strBb, strBh, strCb, strCh;
    int  Hh, M, Nn, K, act;   // act: 0=none, 1=gelu(exact)
    float alpha;
};

__global__ void __launch_bounds__(256) gemm_k(GP p) {
    int z  = blockIdx.z;
    int bb = z / p.Hh, hh = z % p.Hh;
    const float* __restrict__ A  = p.A  + (long)bb * p.strAb + (long)hh * p.strAh;
    const float* __restrict__ Bp = p.Bm + (long)bb * p.strBb + (long)hh * p.strBh;
    float*       Cp = p.Cm + (long)bb * p.strCb + (long)hh * p.strCh;

    int m0 = blockIdx.y * 64, n0 = blockIdx.x * 64;
    __shared__ float As[16][68];
    __shared__ float Bs[16][68];

    int tid = threadIdx.x;
    int tx = tid & 15, ty = tid >> 4;

    unsigned long long acc[2][4];
#pragma unroll
    for (int i = 0; i < 2; i++)
#pragma unroll
        for (int j = 0; j < 4; j++) acc[i][j] = 0ull;

    int nkt = (p.K + 15) >> 4;
    for (int kt = 0; kt < nkt; kt++) {
        int kbase = kt << 4;
#pragma unroll
        for (int l = 0; l < 4; l++) {
            int idx = tid + l * 256;
            int ml = idx >> 4, kl = idx & 15;
            int gk = kbase + kl;
            // A tile
            int gm = m0 + ml;
            float va = 0.f;
            if (gm < p.M && gk < p.K) {
                va = __ldg(A + (long)gm * p.sAm + (long)gk * p.sAk);
                if (p.mu) va = (va - g_mu[gm]) * g_rstd[gm] * p.lnw[gk] + p.lnb[gk];
            }
            As[kl][ml] = va;
            // B tile
            int gn = n0 + ml;
            float vb = 0.f;
            if (gn < p.Nn && gk < p.K)
                vb = __ldg(Bp + (long)gn * p.sBn + (long)gk * p.sBk);
            Bs[kl][ml] = vb;
        }
        __syncthreads();
#pragma unroll
        for (int kk = 0; kk < 16; kk++) {
            const unsigned long long* arow =
                reinterpret_cast<const unsigned long long*>(&As[kk][ty * 4]);
            unsigned long long a0 = arow[0];
            unsigned long long a1 = arow[1];
            float4 bv = *reinterpret_cast<const float4*>(&Bs[kk][tx * 4]);
            unsigned long long b0 = pk2(bv.x), b1 = pk2(bv.y),
                               b2 = pk2(bv.z), b3 = pk2(bv.w);
            fma2(acc[0][0], a0, b0); fma2(acc[0][1], a0, b1);
            fma2(acc[0][2], a0, b2); fma2(acc[0][3], a0, b3);
            fma2(acc[1][0], a1, b0); fma2(acc[1][1], a1, b1);
            fma2(acc[1][2], a1, b2); fma2(acc[1][3], a1, b3);
        }
        __syncthreads();
    }

#pragma unroll
    for (int pi = 0; pi < 2; pi++) {
#pragma unroll
        for (int j = 0; j < 4; j++) {
            float2 v = unpk(acc[pi][j]);
            int gn = n0 + tx * 4 + j;
            int gm = m0 + ty * 4 + pi * 2;
            if (gn < p.Nn) {
                float bia = p.bias ? p.bias[gn] : 0.f;
#pragma unroll
                for (int e = 0; e < 2; e++) {
                    float r = (e == 0 ? v.x : v.y) * p.alpha + bia;
                    if (p.act == 1)
                        r = 0.5f * r * (1.0f + erff(r * 0.7071067811865476f));
                    int gme = gm + e;
                    if (gme < p.M)
                        Cp[(long)gme * p.sCm + (long)gn * p.sCn] = r;
                }
            }
        }
    }
}

// ---------------------------------------------------------------------------
// Kernel: softmax over rows of length 196 (in place)
// ---------------------------------------------------------------------------
__global__ void softmax196_k(float* __restrict__ S, int rows) {
    int row  = blockIdx.x * 4 + (threadIdx.x >> 5);
    int lane = threadIdx.x & 31;
    if (row >= rows) return;
    float* r = S + (long)row * 196;
    float v[7];
    float mx = -INFINITY;
#pragma unroll
    for (int j = 0; j < 7; j++) {
        int i = lane + 32 * j;
        v[j] = (i < 196) ? r[i] : -INFINITY;
        mx = fmaxf(mx, v[j]);
    }
#pragma unroll
    for (int o = 16; o; o >>= 1) mx = fmaxf(mx, __shfl_xor_sync(0xffffffffu, mx, o));
    float s = 0.f;
#pragma unroll
    for (int j = 0; j < 7; j++) {
        int i = lane + 32 * j;
        v[j] = (i < 196) ? expf(v[j] - mx) : 0.f;
        s += v[j];
    }
#pragma unroll
    for (int o = 16; o; o >>= 1) s += __shfl_xor_sync(0xffffffffu, s, o);
    float inv = 1.0f / s;
#pragma unroll
    for (int j = 0; j < 7; j++) {
        int i = lane + 32 * j;
        if (i < 196) r[i] = v[j] * inv;
    }
}

// ---------------------------------------------------------------------------
// Kernel: gather rows of g_kv at given token indices
// ---------------------------------------------------------------------------
__global__ void gather_k(const int* __restrict__ idx, float* __restrict__ dst,
                         int ncols) {
    int b = blockIdx.x / NTc, j = blockIdx.x % NTc;
    const float* src = g_kv + ((long)b * Nc + idx[j]) * C2c;
    float* d = dst + (long)blockIdx.x * ncols;
    for (int c = threadIdx.x; c < ncols; c += blockDim.x) d[c] = src[c];
}

// ---------------------------------------------------------------------------
// Kernel: centroid = idxs[argmax_n mean_h S2[b,h,m,n]] with first-max ties
// ---------------------------------------------------------------------------
__global__ void centroid_k(const int* __restrict__ idxs) {
    int b = blockIdx.x / NTc, m = blockIdx.x % NTc;
    __shared__ float val[256];
    __shared__ int   vid[256];
    int t = threadIdx.x;
    float s = -INFINITY;
    int id = 0x7fffffff;
    if (t < 196) {
        float acc = 0.f;
#pragma unroll
        for (int h = 0; h < 8; h++)
            acc += g_S[(((long)b * 8 + h) * 196 + m) * 196 + t];
        s = acc * 0.125f;
        id = t;
    }
    val[t] = s; vid[t] = id;
    __syncthreads();
    for (int stp = 128; stp; stp >>= 1) {
        if (t < stp) {
            float vo = val[t + stp]; int io = vid[t + stp];
            if (vo > val[t] || (vo == val[t] && io < vid[t])) {
                val[t] = vo; vid[t] = io;
            }
        }
        __syncthreads();
    }
    if (t == 0) g_cent[blockIdx.x] = idxs[vid[0]];
}

// ---------------------------------------------------------------------------
// Kernel: stage-3 windowed attention.
// The -1e9 mask makes softmax over N exactly equal to softmax over the
// <=169 window positions (exp underflows to 0). Dedup needed only for
// indices clipped to 0 or N-1 (each distinct position counted once).
// ---------------------------------------------------------------------------
__global__ void __launch_bounds__(256) stage3_k() {
    int bm = blockIdx.x;
    int b  = bm / NTc;
    __shared__ float qrow[384];
    __shared__ int   adj[169];
    __shared__ unsigned char vld[169];
    __shared__ float sc[169];
    __shared__ float red[256];
    __shared__ float pacc[192];
    __shared__ int   mins[2];
    int t = threadIdx.x;

    if (t < 2) mins[t] = 0x7fffffff;
    for (int i = t; i < 384; i += 256) qrow[i] = g_q2[(long)bm * 384 + i];
    __syncthreads();

    int c = g_cent[bm];
    if (t < 169) {
        int r  = t / 13 - 6;
        int cl = t % 13 - 6;
        int raw = c + (cl - 56 * r);
        int a = min(max(raw, 0), Nc - 1);
        adj[t] = a;
        if (raw <= 0)       atomicMin(&mins[0], t);
        if (raw >= Nc - 1)  atomicMin(&mins[1], t);
    }
    __syncthreads();
    if (t < 169) {
        int a = adj[t];
        unsigned char v = 1;
        if (a == 0      && t != mins[0]) v = 0;
        if (a == Nc - 1 && t != mins[1]) v = 0;
        vld[t] = v;
    }
    __syncthreads();

    const float* kvb = g_kv + (long)b * Nc * C2c;

    for (int h = 0; h < 8; h++) {
        float sv = -INFINITY;
        if (t < 169 && vld[t]) {
            const float4* kr = reinterpret_cast<const float4*>(
                kvb + (long)adj[t] * C2c + h * 48);
            const float4* qh = reinterpret_cast<const float4*>(qrow + h * 48);
            float d0 = 0.f;
#pragma unroll
            for (int j = 0; j < 12; j++) {
                float4 kq = kr[j], qq = qh[j];
                d0 += kq.x * qq.x + kq.y * qq.y + kq.z * qq.z + kq.w * qq.w;
            }
            sv = d0 * SCALE;
        }
        red[t] = sv;
        __syncthreads();
        for (int stp = 128; stp; stp >>= 1) {
            if (t < stp) red[t] = fmaxf(red[t], red[t + stp]);
            __syncthreads();
        }
        float mx = red[0];
        __syncthreads();
        float pv = 0.f;
        if (t < 169 && vld[t]) pv = expf(sv - mx);
        if (t < 169) sc[t] = pv;
        red[t] = pv;
        __syncthreads();
        for (int stp = 128; stp; stp >>= 1) {
            if (t < stp) red[t] += red[t + stp];
            __syncthreads();
        }
        float sm = red[0];
        __syncthreads();
        if (t < 192) {
            int g = t / 48, d = t % 48;
            float acc = 0.f;
            for (int i = g; i < 169; i += 4)
                acc += sc[i] * kvb[(long)adj[i] * C2c + 384 + h * 48 + d];
            pacc[t] = acc;
        }
        __syncthreads();
        if (t < 48) {
            float o = (pacc[t] + pacc[48 + t] + pacc[96 + t] + pacc[144 + t]) / sm;
            g_att[(long)bm * 384 + h * 48 + t] = o;
        }
        __syncthreads();
    }
}

// ---------------------------------------------------------------------------
// Host launch
// ---------------------------------------------------------------------------
static float* symf(const void* sym) {
    void* p = nullptr;
    cudaGetSymbolAddress(&p, sym);
    return (float*)p;
}

static void launch_gemm(const GP& p, int Z) {
    dim3 g((p.Nn + 63) / 64, (p.M + 63) / 64, Z);
    gemm_k<<<g, 256>>>(p);
}

extern "C" void kernel_launch(void* const* d_in, const int* in_sizes, int n_in,
                              void* d_out, int out_size) {
    (void)in_sizes; (void)n_in; (void)out_size;
    const float* x      = (const float*)d_in[0];
    const float* q      = (const float*)d_in[1];
    const float* kv_w   = (const float*)d_in[2];
    const float* proj_w = (const float*)d_in[3];
    const float* proj_b = (const float*)d_in[4];
    const float* ln_w   = (const float*)d_in[5];
    const float* ln_b   = (const float*)d_in[6];
    const float* fc1_w  = (const float*)d_in[7];
    const float* fc1_b  = (const float*)d_in[8];
    const float* fc2_w  = (const float*)d_in[9];
    const float* fc2_b  = (const float*)d_in[10];
    const int*   idx_sub= (const int*)d_in[11];
    const int*   idxs   = (const int*)d_in[12];
    float* out = (float*)d_out;

    float* p_mu    = symf(g_mu);
    float* p_rstd  = symf(g_rstd);
    float* p_kv    = symf(g_kv);
    float* p_kvsub = symf(g_kvsub);
    float* p_kidx  = symf(g_kidx);
    float* p_S     = symf(g_S);
    float* p_q1    = symf(g_q1);
    float* p_h     = symf(g_h);
    float* p_q2    = symf(g_q2);
    float* p_att   = symf(g_att);

    // 1. LN stats
    ln_stats_k<<<(Bc * Nc) / 4, 128>>>(x);

    // 2. KV GEMM with fused LayerNorm: g_kv = LN(x) @ kv_w.T   (100352 x 768, K=384)
    {
        GP p = {};
        p.A = x; p.Bm = kv_w; p.Cm = p_kv;
        p.mu = p_mu; p.rstd = p_rstd; p.lnw = ln_w; p.lnb = ln_b;
        p.sAm = Cc; p.sAk = 1; p.sBn = Cc; p.sBk = 1; p.sCm = C2c; p.sCn = 1;
        p.Hh = 1; p.M = Bc * Nc; p.Nn = C2c; p.K = Cc; p.alpha = 1.f;
        launch_gemm(p, 1);
    }

    // 3. Gather k/v at idx_sub, k at idxs
    gather_k<<<Bc * NTc, 256>>>(idx_sub, p_kvsub, C2c);
    gather_k<<<Bc * NTc, 256>>>(idxs,    p_kidx,  Cc);

    // 4. attn1 scores: S[b,h,m,n] = scale * q[m,h,:] . ksub[b,n,h,:]
    {
        GP p = {};
        p.A = q; p.Bm = p_kvsub; p.Cm = p_S;
        p.sAm = 384; p.sAk = 1; p.strAb = 0;            p.strAh = 48;
        p.sBn = 768; p.sBk = 1; p.strBb = (long)NTc*768; p.strBh = 48;
        p.sCm = 196; p.sCn = 1; p.strCb = (long)8*196*196; p.strCh = (long)196*196;
        p.Hh = 8; p.M = 196; p.Nn = 196; p.K = 48; p.alpha = SCALE;
        launch_gemm(p, Bc * Hc);
    }

    // 5. softmax attn1
    softmax196_k<<<(Bc * Hc * NTc) / 4, 128>>>(p_S, Bc * Hc * NTc);

    // 6. q1[b,m,h*48+d] = sum_n P[b,h,m,n] * vsub[b,n,h,d]
    {
        GP p = {};
        p.A = p_S; p.Bm = p_kvsub + 384; p.Cm = p_q1;
        p.sAm = 196; p.sAk = 1;   p.strAb = (long)8*196*196; p.strAh = (long)196*196;
        p.sBn = 1;   p.sBk = 768; p.strBb = (long)NTc*768;   p.strBh = 48;
        p.sCm = 384; p.sCn = 1;   p.strCb = (long)NTc*384;   p.strCh = 48;
        p.Hh = 8; p.M = 196; p.Nn = 48; p.K = 196; p.alpha = 1.f;
        launch_gemm(p, Bc * Hc);
    }

    // 7. fc1 + exact gelu
    {
        GP p = {};
        p.A = p_q1; p.Bm = fc1_w; p.Cm = p_h; p.bias = fc1_b; p.act = 1;
        p.sAm = Cc; p.sAk = 1; p.sBn = Cc; p.sBk = 1; p.sCm = C2c; p.sCn = 1;
        p.Hh = 1; p.M = Bc * NTc; p.Nn = C2c; p.K = Cc; p.alpha = 1.f;
        launch_gemm(p, 1);
    }

    // 8. fc2
    {
        GP p = {};
        p.A = p_h; p.Bm = fc2_w; p.Cm = p_q2; p.bias = fc2_b;
        p.sAm = C2c; p.sAk = 1; p.sBn = C2c; p.sBk = 1; p.sCm = Cc; p.sCn = 1;
        p.Hh = 1; p.M = Bc * NTc; p.Nn = Cc; p.K = C2c; p.alpha = 1.f;
        launch_gemm(p, 1);
    }

    // 9. attn2 scores (no scale): S[b,h,m,n] = q2[b,m,h,:] . kidx[b,n,h,:]
    {
        GP p = {};
        p.A = p_q2; p.Bm = p_kidx; p.Cm = p_S;
        p.sAm = 384; p.sAk = 1; p.strAb = (long)NTc*384; p.strAh = 48;
        p.sBn = 384; p.sBk = 1; p.strBb = (long)NTc*384; p.strBh = 48;
        p.sCm = 196; p.sCn = 1; p.strCb = (long)8*196*196; p.strCh = (long)196*196;
        p.Hh = 8; p.M = 196; p.Nn = 196; p.K = 48; p.alpha = 1.f;
        launch_gemm(p, Bc * Hc);
    }

    // 10. centroids (argmax with first-max tie-break over mean_h)
    centroid_k<<<Bc * NTc, 256>>>(idxs);

    // 11. stage-3 windowed attention -> g_att
    stage3_k<<<Bc * NTc, 256>>>();

    // 12. output projection
    {
        GP p = {};
        p.A = p_att; p.Bm = proj_w; p.Cm = out; p.bias = proj_b;
        p.sAm = Cc; p.sAk = 1; p.sBn = Cc; p.sBk = 1; p.sCm = Cc; p.sCn = 1;
        p.Hh = 1; p.M = Bc * NTc; p.Nn = Cc; p.K = Cc; p.alpha = 1.f;
        launch_gemm(p, 1);
    }
}

// round 6
// speedup vs baseline: 1.4194x; 1.4194x over previous
#include <cuda_runtime.h>
#include <math.h>

// ---------------------------------------------------------------------------
// Problem constants
// ---------------------------------------------------------------------------
static const int Bc   = 32;      // batch
static const int Nc   = 3136;    // tokens
static const int Cc   = 384;     // channels
static const int Hc   = 8;       // heads
static const int NTc  = 196;     // query tokens
static const int C2c  = 768;     // 2*C
static const float SCALE = 0.14433756729740643f; // 1/sqrt(48)

// ---------------------------------------------------------------------------
// Device scratch
// ---------------------------------------------------------------------------
__device__ float g_mu   [Bc * Nc];
__device__ float g_rstd [Bc * Nc];
__device__ float g_kv   [(size_t)Bc * Nc * C2c];
__device__ float g_kvsub[Bc * NTc * C2c];
__device__ float g_kidx [Bc * NTc * Cc];
__device__ float g_S    [Bc * Hc * NTc * NTc];
__device__ float g_q1   [Bc * NTc * Cc];
__device__ float g_h    [Bc * NTc * C2c];
__device__ float g_q2   [Bc * NTc * Cc];
__device__ int   g_cent [Bc * NTc];
__device__ float g_att  [Bc * NTc * Cc];

// ---------------------------------------------------------------------------
// f32x2 helpers
// ---------------------------------------------------------------------------
__device__ __forceinline__ unsigned long long pk2(float x) {
    unsigned long long r;
    unsigned int u = __float_as_uint(x);
    asm("mov.b64 %0, {%1, %1};" : "=l"(r) : "r"(u));
    return r;
}
__device__ __forceinline__ void fma2(unsigned long long& d,
                                     unsigned long long a,
                                     unsigned long long b) {
    asm("fma.rn.f32x2 %0, %1, %2, %3;" : "=l"(d) : "l"(a), "l"(b), "l"(d));
}
__device__ __forceinline__ float2 unpk(unsigned long long v) {
    unsigned int lo, hi;
    asm("mov.b64 {%0, %1}, %2;" : "=r"(lo), "=r"(hi) : "l"(v));
    return make_float2(__uint_as_float(lo), __uint_as_float(hi));
}

// ---------------------------------------------------------------------------
// LayerNorm statistics
// ---------------------------------------------------------------------------
__global__ void ln_stats_k(const float* __restrict__ x) {
    int row  = blockIdx.x * 4 + (threadIdx.x >> 5);
    int lane = threadIdx.x & 31;
    if (row >= Bc * Nc) return;
    const float* xr = x + (size_t)row * Cc;
    float s = 0.f, s2 = 0.f;
#pragma unroll
    for (int j = 0; j < 12; j++) {
        float v = __ldg(xr + lane + 32 * j);
        s += v; s2 += v * v;
    }
#pragma unroll
    for (int o = 16; o; o >>= 1) {
        s  += __shfl_xor_sync(0xffffffffu, s,  o);
        s2 += __shfl_xor_sync(0xffffffffu, s2, o);
    }
    if (lane == 0) {
        float m   = s * (1.0f / 384.0f);
        float var = s2 * (1.0f / 384.0f) - m * m;
        g_mu[row]   = m;
        g_rstd[row] = rsqrtf(var + 1e-6f);
    }
}

// ---------------------------------------------------------------------------
// Big GEMM: 128x128x16 tile, 256 threads, 8x8 per thread, f32x2 FFMA2.
// Requires M%128==0, N%128==0, K%16==0 (all call sites satisfy this).
// C[m,n] = act( sum_k A[m,k]*B[n,k] + bias[n] ),  A row-major [M,K], B [N,K].
// LNA: apply LayerNorm to A rows on load (uses g_mu/g_rstd + lnw/lnb).
// ---------------------------------------------------------------------------
template<bool LNA, bool DOBIAS, bool DOGELU>
__global__ void __launch_bounds__(256, 2) gemm128_k(
    const float* __restrict__ A, const float* __restrict__ B,
    float* __restrict__ C, const float* __restrict__ bias,
    const float* __restrict__ lnw, const float* __restrict__ lnb,
    int N, int K)
{
    __shared__ float As[16][132];                     // [k][m]
    __shared__ unsigned long long Bsd[16][130];       // [k][n], duplicated {b,b}

    const int tid = threadIdx.x;
    const int m0 = blockIdx.y * 128, n0 = blockIdx.x * 128;
    const int lq = tid & 3, lr = tid >> 2;            // loader: k-quad, row

    const float* Ap0 = A + (size_t)(m0 + lr) * K + lq * 4;
    const float* Ap1 = Ap0 + (size_t)64 * K;
    const float* Bp0 = B + (size_t)(n0 + lr) * K + lq * 4;
    const float* Bp1 = Bp0 + (size_t)64 * K;

    float mu0 = 0.f, rs0 = 0.f, mu1 = 0.f, rs1 = 0.f;
    if (LNA) {
        mu0 = g_mu[m0 + lr];      rs0 = g_rstd[m0 + lr];
        mu1 = g_mu[m0 + lr + 64]; rs1 = g_rstd[m0 + lr + 64];
    }

    const int tx = tid & 15, ty = tid >> 4;           // compute: n-group, m-group

    unsigned long long acc[4][8];                     // [m-pair][n]
#pragma unroll
    for (int i = 0; i < 4; i++)
#pragma unroll
        for (int j = 0; j < 8; j++) acc[i][j] = 0ull;

    // prefetch tile 0
    float4 a0 = *(const float4*)Ap0;
    float4 a1 = *(const float4*)Ap1;
    float4 b0 = *(const float4*)Bp0;
    float4 b1 = *(const float4*)Bp1;
    float4 w4 = make_float4(0,0,0,0), l4 = make_float4(0,0,0,0);
    if (LNA) {
        w4 = *(const float4*)(lnw + lq * 4);
        l4 = *(const float4*)(lnb + lq * 4);
    }

    const int nkt = K >> 4;
    for (int kt = 0; kt < nkt; kt++) {
        // ---- store current tile to smem (LN applied to A here) ----
        float4 va0 = a0, va1 = a1;
        if (LNA) {
            va0.x = (a0.x - mu0) * rs0 * w4.x + l4.x;
            va0.y = (a0.y - mu0) * rs0 * w4.y + l4.y;
            va0.z = (a0.z - mu0) * rs0 * w4.z + l4.z;
            va0.w = (a0.w - mu0) * rs0 * w4.w + l4.w;
            va1.x = (a1.x - mu1) * rs1 * w4.x + l4.x;
            va1.y = (a1.y - mu1) * rs1 * w4.y + l4.y;
            va1.z = (a1.z - mu1) * rs1 * w4.z + l4.z;
            va1.w = (a1.w - mu1) * rs1 * w4.w + l4.w;
        }
        As[lq*4+0][lr]      = va0.x; As[lq*4+1][lr]      = va0.y;
        As[lq*4+2][lr]      = va0.z; As[lq*4+3][lr]      = va0.w;
        As[lq*4+0][lr+64]   = va1.x; As[lq*4+1][lr+64]   = va1.y;
        As[lq*4+2][lr+64]   = va1.z; As[lq*4+3][lr+64]   = va1.w;
        Bsd[lq*4+0][lr]     = pk2(b0.x); Bsd[lq*4+1][lr]     = pk2(b0.y);
        Bsd[lq*4+2][lr]     = pk2(b0.z); Bsd[lq*4+3][lr]     = pk2(b0.w);
        Bsd[lq*4+0][lr+64]  = pk2(b1.x); Bsd[lq*4+1][lr+64]  = pk2(b1.y);
        Bsd[lq*4+2][lr+64]  = pk2(b1.z); Bsd[lq*4+3][lr+64]  = pk2(b1.w);
        __syncthreads();

        // ---- prefetch next tile into registers (latency hidden by compute) ----
        if (kt + 1 < nkt) {
            Ap0 += 16; Ap1 += 16; Bp0 += 16; Bp1 += 16;
            a0 = *(const float4*)Ap0;
            a1 = *(const float4*)Ap1;
            b0 = *(const float4*)Bp0;
            b1 = *(const float4*)Bp1;
            if (LNA) {
                w4 = *(const float4*)(lnw + (kt + 1) * 16 + lq * 4);
                l4 = *(const float4*)(lnb + (kt + 1) * 16 + lq * 4);
            }
        }

        // ---- compute 16 k-steps ----
#pragma unroll
        for (int kk = 0; kk < 16; kk++) {
            const float* ar = &As[kk][ty * 8];
            float4 af0 = *(const float4*)ar;
            float4 af1 = *(const float4*)(ar + 4);
            unsigned long long ap[4];
            ap[0] = *(const unsigned long long*)&af0.x;
            ap[1] = *(const unsigned long long*)&af0.z;
            ap[2] = *(const unsigned long long*)&af1.x;
            ap[3] = *(const unsigned long long*)&af1.z;
            unsigned long long bp[8];
#pragma unroll
            for (int j = 0; j < 8; j++)
                bp[j] = Bsd[kk][tx + 16 * j];
#pragma unroll
            for (int i = 0; i < 4; i++)
#pragma unroll
                for (int j = 0; j < 8; j++)
                    fma2(acc[i][j], ap[i], bp[j]);
        }
        __syncthreads();
    }

    // ---- epilogue: lanes write consecutive n (coalesced) ----
#pragma unroll
    for (int i = 0; i < 4; i++) {
        int gm0 = m0 + ty * 8 + 2 * i;
        float* c0 = C + (size_t)gm0 * N + n0;
        float* c1 = c0 + N;
#pragma unroll
        for (int j = 0; j < 8; j++) {
            float2 v = unpk(acc[i][j]);
            int nn = tx + 16 * j;
            if (DOBIAS) {
                float bia = bias[n0 + nn];
                v.x += bia; v.y += bia;
            }
            if (DOGELU) {
                v.x = 0.5f * v.x * (1.0f + erff(v.x * 0.7071067811865476f));
                v.y = 0.5f * v.y * (1.0f + erff(v.y * 0.7071067811865476f));
            }
            c0[nn] = v.x;
            c1[nn] = v.y;
        }
    }
}

// ---------------------------------------------------------------------------
// Generic small GEMM (64x64 tile) — used for the batched attention GEMMs
// ---------------------------------------------------------------------------
struct GP {
    const float* A; const float* Bm; float* Cm;
    const float* bias;
    long sAm, sAk, sBn, sBk, sCm, sCn;
    long strAb, strAh, strBb, strBh, strCb, strCh;
    int  Hh, M, Nn, K;
    float alpha;
};

__global__ void __launch_bounds__(256) gemm_k(GP p) {
    int z  = blockIdx.z;
    int bb = z / p.Hh, hh = z % p.Hh;
    const float* __restrict__ A  = p.A  + (long)bb * p.strAb + (long)hh * p.strAh;
    const float* __restrict__ Bp = p.Bm + (long)bb * p.strBb + (long)hh * p.strBh;
    float*       Cp = p.Cm + (long)bb * p.strCb + (long)hh * p.strCh;

    int m0 = blockIdx.y * 64, n0 = blockIdx.x * 64;
    __shared__ float As[16][68];
    __shared__ float Bs[16][68];

    int tid = threadIdx.x;
    int tx = tid & 15, ty = tid >> 4;

    unsigned long long acc[2][4];
#pragma unroll
    for (int i = 0; i < 2; i++)
#pragma unroll
        for (int j = 0; j < 4; j++) acc[i][j] = 0ull;

    int nkt = (p.K + 15) >> 4;
    for (int kt = 0; kt < nkt; kt++) {
        int kbase = kt << 4;
#pragma unroll
        for (int l = 0; l < 4; l++) {
            int idx = tid + l * 256;
            int ml = idx >> 4, kl = idx & 15;
            int gk = kbase + kl;
            int gm = m0 + ml;
            float va = 0.f;
            if (gm < p.M && gk < p.K)
                va = __ldg(A + (long)gm * p.sAm + (long)gk * p.sAk);
            As[kl][ml] = va;
            int gn = n0 + ml;
            float vb = 0.f;
            if (gn < p.Nn && gk < p.K)
                vb = __ldg(Bp + (long)gn * p.sBn + (long)gk * p.sBk);
            Bs[kl][ml] = vb;
        }
        __syncthreads();
#pragma unroll
        for (int kk = 0; kk < 16; kk++) {
            const unsigned long long* arow =
                reinterpret_cast<const unsigned long long*>(&As[kk][ty * 4]);
            unsigned long long a0 = arow[0];
            unsigned long long a1 = arow[1];
            float4 bv = *reinterpret_cast<const float4*>(&Bs[kk][tx * 4]);
            unsigned long long b0 = pk2(bv.x), b1 = pk2(bv.y),
                               b2 = pk2(bv.z), b3 = pk2(bv.w);
            fma2(acc[0][0], a0, b0); fma2(acc[0][1], a0, b1);
            fma2(acc[0][2], a0, b2); fma2(acc[0][3], a0, b3);
            fma2(acc[1][0], a1, b0); fma2(acc[1][1], a1, b1);
            fma2(acc[1][2], a1, b2); fma2(acc[1][3], a1, b3);
        }
        __syncthreads();
    }

#pragma unroll
    for (int pi = 0; pi < 2; pi++) {
#pragma unroll
        for (int j = 0; j < 4; j++) {
            float2 v = unpk(acc[pi][j]);
            int gn = n0 + tx * 4 + j;
            int gm = m0 + ty * 4 + pi * 2;
            if (gn < p.Nn) {
                float bia = p.bias ? p.bias[gn] : 0.f;
#pragma unroll
                for (int e = 0; e < 2; e++) {
                    float r = (e == 0 ? v.x : v.y) * p.alpha + bia;
                    int gme = gm + e;
                    if (gme < p.M)
                        Cp[(long)gme * p.sCm + (long)gn * p.sCn] = r;
                }
            }
        }
    }
}

// ---------------------------------------------------------------------------
// softmax over rows of length 196 (in place)
// ---------------------------------------------------------------------------
__global__ void softmax196_k(float* __restrict__ S, int rows) {
    int row  = blockIdx.x * 4 + (threadIdx.x >> 5);
    int lane = threadIdx.x & 31;
    if (row >= rows) return;
    float* r = S + (long)row * 196;
    float v[7];
    float mx = -INFINITY;
#pragma unroll
    for (int j = 0; j < 7; j++) {
        int i = lane + 32 * j;
        v[j] = (i < 196) ? r[i] : -INFINITY;
        mx = fmaxf(mx, v[j]);
    }
#pragma unroll
    for (int o = 16; o; o >>= 1) mx = fmaxf(mx, __shfl_xor_sync(0xffffffffu, mx, o));
    float s = 0.f;
#pragma unroll
    for (int j = 0; j < 7; j++) {
        int i = lane + 32 * j;
        v[j] = (i < 196) ? expf(v[j] - mx) : 0.f;
        s += v[j];
    }
#pragma unroll
    for (int o = 16; o; o >>= 1) s += __shfl_xor_sync(0xffffffffu, s, o);
    float inv = 1.0f / s;
#pragma unroll
    for (int j = 0; j < 7; j++) {
        int i = lane + 32 * j;
        if (i < 196) r[i] = v[j] * inv;
    }
}

// ---------------------------------------------------------------------------
// gather rows of g_kv at given token indices
// ---------------------------------------------------------------------------
__global__ void gather_k(const int* __restrict__ idx, float* __restrict__ dst,
                         int ncols) {
    int b = blockIdx.x / NTc, j = blockIdx.x % NTc;
    const float* src = g_kv + ((long)b * Nc + idx[j]) * C2c;
    float* d = dst + (long)blockIdx.x * ncols;
    for (int c = threadIdx.x; c < ncols; c += blockDim.x) d[c] = src[c];
}

// ---------------------------------------------------------------------------
// centroid = idxs[argmax_n mean_h S2[b,h,m,n]] with first-max ties
// ---------------------------------------------------------------------------
__global__ void centroid_k(const int* __restrict__ idxs) {
    int b = blockIdx.x / NTc, m = blockIdx.x % NTc;
    __shared__ float val[256];
    __shared__ int   vid[256];
    int t = threadIdx.x;
    float s = -INFINITY;
    int id = 0x7fffffff;
    if (t < 196) {
        float acc = 0.f;
#pragma unroll
        for (int h = 0; h < 8; h++)
            acc += g_S[(((long)b * 8 + h) * 196 + m) * 196 + t];
        s = acc * 0.125f;
        id = t;
    }
    val[t] = s; vid[t] = id;
    __syncthreads();
    for (int stp = 128; stp; stp >>= 1) {
        if (t < stp) {
            float vo = val[t + stp]; int io = vid[t + stp];
            if (vo > val[t] || (vo == val[t] && io < vid[t])) {
                val[t] = vo; vid[t] = io;
            }
        }
        __syncthreads();
    }
    if (t == 0) g_cent[blockIdx.x] = idxs[vid[0]];
}

// ---------------------------------------------------------------------------
// stage-3 windowed attention (softmax over <=169 window == full softmax,
// since exp(-1e9) underflows to exactly 0 in fp32)
// ---------------------------------------------------------------------------
__global__ void __launch_bounds__(256) stage3_k() {
    int bm = blockIdx.x;
    int b  = bm / NTc;
    __shared__ float qrow[384];
    __shared__ int   adj[169];
    __shared__ unsigned char vld[169];
    __shared__ float sc[169];
    __shared__ float red[256];
    __shared__ float pacc[192];
    __shared__ int   mins[2];
    int t = threadIdx.x;

    if (t < 2) mins[t] = 0x7fffffff;
    for (int i = t; i < 384; i += 256) qrow[i] = g_q2[(long)bm * 384 + i];
    __syncthreads();

    int c = g_cent[bm];
    if (t < 169) {
        int r  = t / 13 - 6;
        int cl = t % 13 - 6;
        int raw = c + (cl - 56 * r);
        int a = min(max(raw, 0), Nc - 1);
        adj[t] = a;
        if (raw <= 0)       atomicMin(&mins[0], t);
        if (raw >= Nc - 1)  atomicMin(&mins[1], t);
    }
    __syncthreads();
    if (t < 169) {
        int a = adj[t];
        unsigned char v = 1;
        if (a == 0      && t != mins[0]) v = 0;
        if (a == Nc - 1 && t != mins[1]) v = 0;
        vld[t] = v;
    }
    __syncthreads();

    const float* kvb = g_kv + (long)b * Nc * C2c;

    for (int h = 0; h < 8; h++) {
        float sv = -INFINITY;
        if (t < 169 && vld[t]) {
            const float4* kr = reinterpret_cast<const float4*>(
                kvb + (long)adj[t] * C2c + h * 48);
            const float4* qh = reinterpret_cast<const float4*>(qrow + h * 48);
            float d0 = 0.f;
#pragma unroll
            for (int j = 0; j < 12; j++) {
                float4 kq = kr[j], qq = qh[j];
                d0 += kq.x * qq.x + kq.y * qq.y + kq.z * qq.z + kq.w * qq.w;
            }
            sv = d0 * SCALE;
        }
        red[t] = sv;
        __syncthreads();
        for (int stp = 128; stp; stp >>= 1) {
            if (t < stp) red[t] = fmaxf(red[t], red[t + stp]);
            __syncthreads();
        }
        float mx = red[0];
        __syncthreads();
        float pv = 0.f;
        if (t < 169 && vld[t]) pv = expf(sv - mx);
        if (t < 169) sc[t] = pv;
        red[t] = pv;
        __syncthreads();
        for (int stp = 128; stp; stp >>= 1) {
            if (t < stp) red[t] += red[t + stp];
            __syncthreads();
        }
        float sm = red[0];
        __syncthreads();
        if (t < 192) {
            int g = t / 48, d = t % 48;
            float acc = 0.f;
            for (int i = g; i < 169; i += 4)
                acc += sc[i] * kvb[(long)adj[i] * C2c + 384 + h * 48 + d];
            pacc[t] = acc;
        }
        __syncthreads();
        if (t < 48) {
            float o = (pacc[t] + pacc[48 + t] + pacc[96 + t] + pacc[144 + t]) / sm;
            g_att[(long)bm * 384 + h * 48 + t] = o;
        }
        __syncthreads();
    }
}

// ---------------------------------------------------------------------------
// Host launch
// ---------------------------------------------------------------------------
static float* symf(const void* sym) {
    void* p = nullptr;
    cudaGetSymbolAddress(&p, sym);
    return (float*)p;
}

static void launch_gemm(const GP& p, int Z) {
    dim3 g((p.Nn + 63) / 64, (p.M + 63) / 64, Z);
    gemm_k<<<g, 256>>>(p);
}

extern "C" void kernel_launch(void* const* d_in, const int* in_sizes, int n_in,
                              void* d_out, int out_size) {
    (void)in_sizes; (void)n_in; (void)out_size;
    const float* x      = (const float*)d_in[0];
    const float* q      = (const float*)d_in[1];
    const float* kv_w   = (const float*)d_in[2];
    const float* proj_w = (const float*)d_in[3];
    const float* proj_b = (const float*)d_in[4];
    const float* ln_w   = (const float*)d_in[5];
    const float* ln_b   = (const float*)d_in[6];
    const float* fc1_w  = (const float*)d_in[7];
    const float* fc1_b  = (const float*)d_in[8];
    const float* fc2_w  = (const float*)d_in[9];
    const float* fc2_b  = (const float*)d_in[10];
    const int*   idx_sub= (const int*)d_in[11];
    const int*   idxs   = (const int*)d_in[12];
    float* out = (float*)d_out;

    float* p_kv    = symf(g_kv);
    float* p_kvsub = symf(g_kvsub);
    float* p_kidx  = symf(g_kidx);
    float* p_S     = symf(g_S);
    float* p_q1    = symf(g_q1);
    float* p_h     = symf(g_h);
    float* p_q2    = symf(g_q2);
    float* p_att   = symf(g_att);

    // 1. LN stats
    ln_stats_k<<<(Bc * Nc) / 4, 128>>>(x);

    // 2. KV GEMM with fused LayerNorm: g_kv = LN(x) @ kv_w.T  (100352 x 768, K=384)
    gemm128_k<true, false, false><<<dim3(C2c / 128, (Bc * Nc) / 128), 256>>>(
        x, kv_w, p_kv, nullptr, ln_w, ln_b, C2c, Cc);

    // 3. Gathers
    gather_k<<<Bc * NTc, 256>>>(idx_sub, p_kvsub, C2c);
    gather_k<<<Bc * NTc, 256>>>(idxs,    p_kidx,  Cc);

    // 4. attn1 scores
    {
        GP p = {};
        p.A = q; p.Bm = p_kvsub; p.Cm = p_S;
        p.sAm = 384; p.sAk = 1; p.strAb = 0;             p.strAh = 48;
        p.sBn = 768; p.sBk = 1; p.strBb = (long)NTc*768; p.strBh = 48;
        p.sCm = 196; p.sCn = 1; p.strCb = (long)8*196*196; p.strCh = (long)196*196;
        p.Hh = 8; p.M = 196; p.Nn = 196; p.K = 48; p.alpha = SCALE;
        launch_gemm(p, Bc * Hc);
    }

    // 5. softmax attn1
    softmax196_k<<<(Bc * Hc * NTc) / 4, 128>>>(p_S, Bc * Hc * NTc);

    // 6. P @ V
    {
        GP p = {};
        p.A = p_S; p.Bm = p_kvsub + 384; p.Cm = p_q1;
        p.sAm = 196; p.sAk = 1;   p.strAb = (long)8*196*196; p.strAh = (long)196*196;
        p.sBn = 1;   p.sBk = 768; p.strBb = (long)NTc*768;   p.strBh = 48;
        p.sCm = 384; p.sCn = 1;   p.strCb = (long)NTc*384;   p.strCh = 48;
        p.Hh = 8; p.M = 196; p.Nn = 48; p.K = 196; p.alpha = 1.f;
        launch_gemm(p, Bc * Hc);
    }

    // 7. fc1 + exact gelu  (6272 x 768, K=384)
    gemm128_k<false, true, true><<<dim3(C2c / 128, (Bc * NTc) / 128), 256>>>(
        p_q1, fc1_w, p_h, fc1_b, nullptr, nullptr, C2c, Cc);

    // 8. fc2  (6272 x 384, K=768)
    gemm128_k<false, true, false><<<dim3(Cc / 128, (Bc * NTc) / 128), 256>>>(
        p_h, fc2_w, p_q2, fc2_b, nullptr, nullptr, Cc, C2c);

    // 9. attn2 scores
    {
        GP p = {};
        p.A = p_q2; p.Bm = p_kidx; p.Cm = p_S;
        p.sAm = 384; p.sAk = 1; p.strAb = (long)NTc*384; p.strAh = 48;
        p.sBn = 384; p.sBk = 1; p.strBb = (long)NTc*384; p.strBh = 48;
        p.sCm = 196; p.sCn = 1; p.strCb = (long)8*196*196; p.strCh = (long)196*196;
        p.Hh = 8; p.M = 196; p.Nn = 196; p.K = 48; p.alpha = 1.f;
        launch_gemm(p, Bc * Hc);
    }

    // 10. centroids
    centroid_k<<<Bc * NTc, 256>>>(idxs);

    // 11. stage-3 windowed attention
    stage3_k<<<Bc * NTc, 256>>>();

    // 12. output projection  (6272 x 384, K=384)
    gemm128_k<false, true, false><<<dim3(Cc / 128, (Bc * NTc) / 128), 256>>>(
        p_att, proj_w, out, proj_b, nullptr, nullptr, Cc, Cc);
}

// round 14
// speedup vs baseline: 1.5928x; 1.1222x over previous
#include <cuda_runtime.h>
#include <math.h>
#include <stdint.h>
#include <mma.h>

using namespace nvcuda;

// ---------------------------------------------------------------------------
// Problem constants
// ---------------------------------------------------------------------------
static const int Bc   = 32;      // batch
static const int Nc   = 3136;    // tokens
static const int Cc   = 384;     // channels
static const int Hc   = 8;       // heads
static const int NTc  = 196;     // query tokens
static const int C2c  = 768;     // 2*C
static const float SCALE = 0.14433756729740643f; // 1/sqrt(48)

// ---------------------------------------------------------------------------
// Device scratch
// ---------------------------------------------------------------------------
__device__ float g_mu   [Bc * Nc];
__device__ float g_rstd [Bc * Nc];
__device__ float g_kv   [(size_t)Bc * Nc * C2c];   // tf32-accuracy k|v (stage-3 only)
__device__ float g_xns  [Bc * NTc * Cc];           // LN(x) rows at idx_sub (exact)
__device__ float g_xni  [Bc * NTc * Cc];           // LN(x) rows at idxs (exact)
__device__ float g_kvsub[Bc * NTc * C2c];          // exact k|v at idx_sub
__device__ float g_kidx [Bc * NTc * Cc];           // exact k at idxs
__device__ float g_S    [Bc * Hc * NTc * NTc];
__device__ float g_q1   [Bc * NTc * Cc];
__device__ float g_h    [Bc * NTc * C2c];
__device__ float g_q2   [Bc * NTc * Cc];
__device__ int   g_cent [Bc * NTc];
__device__ float g_att  [Bc * NTc * Cc];

// ---------------------------------------------------------------------------
// f32x2 helpers
// ---------------------------------------------------------------------------
__device__ __forceinline__ unsigned long long pk2(float x) {
    unsigned long long r;
    unsigned int u = __float_as_uint(x);
    asm("mov.b64 %0, {%1, %1};" : "=l"(r) : "r"(u));
    return r;
}
__device__ __forceinline__ void fma2(unsigned long long& d,
                                     unsigned long long a,
                                     unsigned long long b) {
    asm("fma.rn.f32x2 %0, %1, %2, %3;" : "=l"(d) : "l"(a), "l"(b), "l"(d));
}
__device__ __forceinline__ float2 unpk(unsigned long long v) {
    unsigned int lo, hi;
    asm("mov.b64 {%0, %1}, %2;" : "=r"(lo), "=r"(hi) : "l"(v));
    return make_float2(__uint_as_float(lo), __uint_as_float(hi));
}
__device__ __forceinline__ float f2tf32f(float v) {
    uint32_t r;
    asm("cvt.rna.tf32.f32 %0, %1;" : "=r"(r) : "f"(v));
    return __uint_as_float(r);
}

// ---------------------------------------------------------------------------
// LayerNorm statistics
// ---------------------------------------------------------------------------
__global__ void ln_stats_k(const float* __restrict__ x) {
    int row  = blockIdx.x * 4 + (threadIdx.x >> 5);
    int lane = threadIdx.x & 31;
    if (row >= Bc * Nc) return;
    const float* xr = x + (size_t)row * Cc;
    float s = 0.f, s2 = 0.f;
#pragma unroll
    for (int j = 0; j < 12; j++) {
        float v = __ldg(xr + lane + 32 * j);
        s += v; s2 += v * v;
    }
#pragma unroll
    for (int o = 16; o; o >>= 1) {
        s  += __shfl_xor_sync(0xffffffffu, s,  o);
        s2 += __shfl_xor_sync(0xffffffffu, s2, o);
    }
    if (lane == 0) {
        float m   = s * (1.0f / 384.0f);
        float var = s2 * (1.0f / 384.0f) - m * m;
        g_mu[row]   = m;
        g_rstd[row] = rsqrtf(var + 1e-6f);
    }
}

// ---------------------------------------------------------------------------
// KV GEMM via wmma tf32 (baseline PTX -> HMMA.1688 on sm_103).
// Per CTA: D[128, 64] = LN(x)[m0:m0+128, :384] @ kv_w[n0:n0+64, :384]^T
// 8 warps, each computes a 32x32 subtile as 2x2 m16n16k8 fragments.
// K staged in chunks of 32 (tf32-converted on smem store; LN fused on A).
// ---------------------------------------------------------------------------
__global__ void __launch_bounds__(256) kv_wmma_k(
    const float* __restrict__ x, const float* __restrict__ w,
    const float* __restrict__ lnw, const float* __restrict__ lnb)
{
    __shared__ float As[128][40];   // [m][k] row-major, pad 40
    __shared__ float Bs[64][40];    // [n][k]  => col-major view of B[k][n], ldm 40

    const int tid = threadIdx.x;
    const int wid = tid >> 5;
    const int m0 = blockIdx.y * 128, n0 = blockIdx.x * 64;
    const int wm = (wid >> 1) * 32, wn = (wid & 1) * 32;

    wmma::fragment<wmma::accumulator, 16, 16, 8, float> c[2][2];
#pragma unroll
    for (int i = 0; i < 2; i++)
#pragma unroll
        for (int j = 0; j < 2; j++)
            wmma::fill_fragment(c[i][j], 0.0f);

    for (int ck = 0; ck < 12; ck++) {
        const int kbase = ck * 32;
        // --- stage A: 128 rows x 32 k (1024 float4, 4 per thread), LN fused ---
#pragma unroll
        for (int l = 0; l < 4; l++) {
            int idx = tid + l * 256;
            int row = idx >> 3, f4 = idx & 7;
            int gm = m0 + row;
            float4 v = *(const float4*)(x + (size_t)gm * 384 + kbase + f4 * 4);
            float4 w4 = *(const float4*)(lnw + kbase + f4 * 4);
            float4 l4 = *(const float4*)(lnb + kbase + f4 * 4);
            float mu = g_mu[gm], rs = g_rstd[gm];
            float* d = &As[row][f4 * 4];
            d[0] = f2tf32f((v.x - mu) * rs * w4.x + l4.x);
            d[1] = f2tf32f((v.y - mu) * rs * w4.y + l4.y);
            d[2] = f2tf32f((v.z - mu) * rs * w4.z + l4.z);
            d[3] = f2tf32f((v.w - mu) * rs * w4.w + l4.w);
        }
        // --- stage B: 64 rows x 32 k (512 float4, 2 per thread) ---
#pragma unroll
        for (int l = 0; l < 2; l++) {
            int idx = tid + l * 256;
            int row = idx >> 3, f4 = idx & 7;
            float4 v = *(const float4*)(w + (size_t)(n0 + row) * 384 + kbase + f4 * 4);
            float* d = &Bs[row][f4 * 4];
            d[0] = f2tf32f(v.x);
            d[1] = f2tf32f(v.y);
            d[2] = f2tf32f(v.z);
            d[3] = f2tf32f(v.w);
        }
        __syncthreads();

        // --- compute: 4 k-steps of 8 ---
#pragma unroll
        for (int ks = 0; ks < 4; ks++) {
            wmma::fragment<wmma::matrix_a, 16, 16, 8, wmma::precision::tf32,
                           wmma::row_major> a[2];
            wmma::fragment<wmma::matrix_b, 16, 16, 8, wmma::precision::tf32,
                           wmma::col_major> b[2];
#pragma unroll
            for (int i = 0; i < 2; i++)
                wmma::load_matrix_sync(a[i], &As[wm + 16 * i][ks * 8], 40);
#pragma unroll
            for (int j = 0; j < 2; j++)
                wmma::load_matrix_sync(b[j], &Bs[wn + 16 * j][ks * 8], 40);
#pragma unroll
            for (int i = 0; i < 2; i++)
#pragma unroll
                for (int j = 0; j < 2; j++)
                    wmma::mma_sync(c[i][j], a[i], b[j], c[i][j]);
        }
        __syncthreads();
    }

    // --- epilogue: direct fragment store, row-major, ldm 768 ---
#pragma unroll
    for (int i = 0; i < 2; i++)
#pragma unroll
        for (int j = 0; j < 2; j++) {
            float* dst = g_kv + (size_t)(m0 + wm + 16 * i) * 768
                              + (n0 + wn + 16 * j);
            wmma::store_matrix_sync(dst, c[i][j], 768, wmma::mem_row_major);
        }
}

// ---------------------------------------------------------------------------
// gather LN(x) rows at token indices (exact fp32 path for argmax stability)
// ---------------------------------------------------------------------------
__global__ void gatherx_k(const float* __restrict__ x, const int* __restrict__ idx,
                          const float* __restrict__ lnw, const float* __restrict__ lnb,
                          float* __restrict__ dst) {
    int b = blockIdx.x / NTc, j = blockIdx.x % NTc;
    int row = idx[j];
    const float* src = x + ((size_t)b * Nc + row) * Cc;
    float mu = g_mu[b * Nc + row], rs = g_rstd[b * Nc + row];
    float* d = dst + (size_t)blockIdx.x * Cc;
    for (int c = threadIdx.x; c < Cc; c += blockDim.x)
        d[c] = (src[c] - mu) * rs * lnw[c] + lnb[c];
}

// ---------------------------------------------------------------------------
// Big fp32 GEMM: 128x128x16 tile, 256 threads, 8x8/thread, f32x2 FFMA2.
// ---------------------------------------------------------------------------
template<bool DOBIAS, bool DOGELU>
__global__ void __launch_bounds__(256, 2) gemm128_k(
    const float* __restrict__ A, const float* __restrict__ B,
    float* __restrict__ C, const float* __restrict__ bias,
    int N, int K)
{
    __shared__ float As[16][132];
    __shared__ unsigned long long Bsd[16][130];

    const int tid = threadIdx.x;
    const int m0 = blockIdx.y * 128, n0 = blockIdx.x * 128;
    const int lq = tid & 3, lr = tid >> 2;

    const float* Ap0 = A + (size_t)(m0 + lr) * K + lq * 4;
    const float* Ap1 = Ap0 + (size_t)64 * K;
    const float* Bp0 = B + (size_t)(n0 + lr) * K + lq * 4;
    const float* Bp1 = Bp0 + (size_t)64 * K;

    const int tx = tid & 15, ty = tid >> 4;

    unsigned long long acc[4][8];
#pragma unroll
    for (int i = 0; i < 4; i++)
#pragma unroll
        for (int j = 0; j < 8; j++) acc[i][j] = 0ull;

    float4 a0 = *(const float4*)Ap0;
    float4 a1 = *(const float4*)Ap1;
    float4 b0 = *(const float4*)Bp0;
    float4 b1 = *(const float4*)Bp1;

    const int nkt = K >> 4;
    for (int kt = 0; kt < nkt; kt++) {
        As[lq*4+0][lr]      = a0.x; As[lq*4+1][lr]      = a0.y;
        As[lq*4+2][lr]      = a0.z; As[lq*4+3][lr]      = a0.w;
        As[lq*4+0][lr+64]   = a1.x; As[lq*4+1][lr+64]   = a1.y;
        As[lq*4+2][lr+64]   = a1.z; As[lq*4+3][lr+64]   = a1.w;
        Bsd[lq*4+0][lr]     = pk2(b0.x); Bsd[lq*4+1][lr]     = pk2(b0.y);
        Bsd[lq*4+2][lr]     = pk2(b0.z); Bsd[lq*4+3][lr]     = pk2(b0.w);
        Bsd[lq*4+0][lr+64]  = pk2(b1.x); Bsd[lq*4+1][lr+64]  = pk2(b1.y);
        Bsd[lq*4+2][lr+64]  = pk2(b1.z); Bsd[lq*4+3][lr+64]  = pk2(b1.w);
        __syncthreads();

        if (kt + 1 < nkt) {
            Ap0 += 16; Ap1 += 16; Bp0 += 16; Bp1 += 16;
            a0 = *(const float4*)Ap0;
            a1 = *(const float4*)Ap1;
            b0 = *(const float4*)Bp0;
            b1 = *(const float4*)Bp1;
        }

#pragma unroll
        for (int kk = 0; kk < 16; kk++) {
            const float* ar = &As[kk][ty * 8];
            float4 af0 = *(const float4*)ar;
            float4 af1 = *(const float4*)(ar + 4);
            unsigned long long ap[4];
            ap[0] = *(const unsigned long long*)&af0.x;
            ap[1] = *(const unsigned long long*)&af0.z;
            ap[2] = *(const unsigned long long*)&af1.x;
            ap[3] = *(const unsigned long long*)&af1.z;
            unsigned long long bp[8];
#pragma unroll
            for (int j = 0; j < 8; j++)
                bp[j] = Bsd[kk][tx + 16 * j];
#pragma unroll
            for (int i = 0; i < 4; i++)
#pragma unroll
                for (int j = 0; j < 8; j++)
                    fma2(acc[i][j], ap[i], bp[j]);
        }
        __syncthreads();
    }

#pragma unroll
    for (int i = 0; i < 4; i++) {
        int gm0 = m0 + ty * 8 + 2 * i;
        float* c0 = C + (size_t)gm0 * N + n0;
        float* c1 = c0 + N;
#pragma unroll
        for (int j = 0; j < 8; j++) {
            float2 v = unpk(acc[i][j]);
            int nn = tx + 16 * j;
            if (DOBIAS) {
                float bia = bias[n0 + nn];
                v.x += bia; v.y += bia;
            }
            if (DOGELU) {
                v.x = 0.5f * v.x * (1.0f + erff(v.x * 0.7071067811865476f));
                v.y = 0.5f * v.y * (1.0f + erff(v.y * 0.7071067811865476f));
            }
            c0[nn] = v.x;
            c1[nn] = v.y;
        }
    }
}

// ---------------------------------------------------------------------------
// Generic small GEMM (64x64 tile) — batched attention GEMMs
// ---------------------------------------------------------------------------
struct GP {
    const float* A; const float* Bm; float* Cm;
    const float* bias;
    long sAm, sAk, sBn, sBk, sCm, sCn;
    long strAb, strAh, strBb, strBh, strCb, strCh;
    int  Hh, M, Nn, K;
    float alpha;
};

__global__ void __launch_bounds__(256) gemm_k(GP p) {
    int z  = blockIdx.z;
    int bb = z / p.Hh, hh = z % p.Hh;
    const float* __restrict__ A  = p.A  + (long)bb * p.strAb + (long)hh * p.strAh;
    const float* __restrict__ Bp = p.Bm + (long)bb * p.strBb + (long)hh * p.strBh;
    float*       Cp = p.Cm + (long)bb * p.strCb + (long)hh * p.strCh;

    int m0 = blockIdx.y * 64, n0 = blockIdx.x * 64;
    __shared__ float As[16][68];
    __shared__ float Bs[16][68];

    int tid = threadIdx.x;
    int tx = tid & 15, ty = tid >> 4;

    unsigned long long acc[2][4];
#pragma unroll
    for (int i = 0; i < 2; i++)
#pragma unroll
        for (int j = 0; j < 4; j++) acc[i][j] = 0ull;

    int nkt = (p.K + 15) >> 4;
    for (int kt = 0; kt < nkt; kt++) {
        int kbase = kt << 4;
#pragma unroll
        for (int l = 0; l < 4; l++) {
            int idx = tid + l * 256;
            int ml = idx >> 4, kl = idx & 15;
            int gk = kbase + kl;
            int gm = m0 + ml;
            float va = 0.f;
            if (gm < p.M && gk < p.K)
                va = __ldg(A + (long)gm * p.sAm + (long)gk * p.sAk);
            As[kl][ml] = va;
            int gn = n0 + ml;
            float vb = 0.f;
            if (gn < p.Nn && gk < p.K)
                vb = __ldg(Bp + (long)gn * p.sBn + (long)gk * p.sBk);
            Bs[kl][ml] = vb;
        }
        __syncthreads();
#pragma unroll
        for (int kk = 0; kk < 16; kk++) {
            const unsigned long long* arow =
                reinterpret_cast<const unsigned long long*>(&As[kk][ty * 4]);
            unsigned long long a0 = arow[0];
            unsigned long long a1 = arow[1];
            float4 bv = *reinterpret_cast<const float4*>(&Bs[kk][tx * 4]);
            unsigned long long b0 = pk2(bv.x), b1 = pk2(bv.y),
                               b2 = pk2(bv.z), b3 = pk2(bv.w);
            fma2(acc[0][0], a0, b0); fma2(acc[0][1], a0, b1);
            fma2(acc[0][2], a0, b2); fma2(acc[0][3], a0, b3);
            fma2(acc[1][0], a1, b0); fma2(acc[1][1], a1, b1);
            fma2(acc[1][2], a1, b2); fma2(acc[1][3], a1, b3);
        }
        __syncthreads();
    }

#pragma unroll
    for (int pi = 0; pi < 2; pi++) {
#pragma unroll
        for (int j = 0; j < 4; j++) {
            float2 v = unpk(acc[pi][j]);
            int gn = n0 + tx * 4 + j;
            int gm = m0 + ty * 4 + pi * 2;
            if (gn < p.Nn) {
                float bia = p.bias ? p.bias[gn] : 0.f;
#pragma unroll
                for (int e = 0; e < 2; e++) {
                    float r = (e == 0 ? v.x : v.y) * p.alpha + bia;
                    int gme = gm + e;
                    if (gme < p.M)
                        Cp[(long)gme * p.sCm + (long)gn * p.sCn] = r;
                }
            }
        }
    }
}

// ---------------------------------------------------------------------------
// softmax over rows of length 196 (in place)
// ---------------------------------------------------------------------------
__global__ void softmax196_k(float* __restrict__ S, int rows) {
    int row  = blockIdx.x * 4 + (threadIdx.x >> 5);
    int lane = threadIdx.x & 31;
    if (row >= rows) return;
    float* r = S + (long)row * 196;
    float v[7];
    float mx = -INFINITY;
#pragma unroll
    for (int j = 0; j < 7; j++) {
        int i = lane + 32 * j;
        v[j] = (i < 196) ? r[i] : -INFINITY;
        mx = fmaxf(mx, v[j]);
    }
#pragma unroll
    for (int o = 16; o; o >>= 1) mx = fmaxf(mx, __shfl_xor_sync(0xffffffffu, mx, o));
    float s = 0.f;
#pragma unroll
    for (int j = 0; j < 7; j++) {
        int i = lane + 32 * j;
        v[j] = (i < 196) ? expf(v[j] - mx) : 0.f;
        s += v[j];
    }
#pragma unroll
    for (int o = 16; o; o >>= 1) s += __shfl_xor_sync(0xffffffffu, s, o);
    float inv = 1.0f / s;
#pragma unroll
    for (int j = 0; j < 7; j++) {
        int i = lane + 32 * j;
        if (i < 196) r[i] = v[j] * inv;
    }
}

// ---------------------------------------------------------------------------
// centroid = idxs[argmax_n mean_h S2[b,h,m,n]] with first-max ties
// ---------------------------------------------------------------------------
__global__ void centroid_k(const int* __restrict__ idxs) {
    int b = blockIdx.x / NTc, m = blockIdx.x % NTc;
    __shared__ float val[256];
    __shared__ int   vid[256];
    int t = threadIdx.x;
    float s = -INFINITY;
    int id = 0x7fffffff;
    if (t < 196) {
        float acc = 0.f;
#pragma unroll
        for (int h = 0; h < 8; h++)
            acc += g_S[(((long)b * 8 + h) * 196 + m) * 196 + t];
        s = acc * 0.125f;
        id = t;
    }
    val[t] = s; vid[t] = id;
    __syncthreads();
    for (int stp = 128; stp; stp >>= 1) {
        if (t < stp) {
            float vo = val[t + stp]; int io = vid[t + stp];
            if (vo > val[t] || (vo == val[t] && io < vid[t])) {
                val[t] = vo; vid[t] = io;
            }
        }
        __syncthreads();
    }
    if (t == 0) g_cent[blockIdx.x] = idxs[vid[0]];
}

// ---------------------------------------------------------------------------
// stage-3 windowed attention (softmax over <=169 window == full softmax,
// since exp(-1e9) underflows to exactly 0 in fp32)
// ---------------------------------------------------------------------------
__global__ void __launch_bounds__(256) stage3_k() {
    int bm = blockIdx.x;
    int b  = bm / NTc;
    __shared__ float qrow[384];
    __shared__ int   adj[169];
    __shared__ unsigned char vld[169];
    __shared__ float sc[169];
    __shared__ float red[256];
    __shared__ float pacc[192];
    __shared__ int   mins[2];
    int t = threadIdx.x;

    if (t < 2) mins[t] = 0x7fffffff;
    for (int i = t; i < 384; i += 256) qrow[i] = g_q2[(long)bm * 384 + i];
    __syncthreads();

    int c = g_cent[bm];
    if (t < 169) {
        int r  = t / 13 - 6;
        int cl = t % 13 - 6;
        int raw = c + (cl - 56 * r);
        int a = min(max(raw, 0), Nc - 1);
        adj[t] = a;
        if (raw <= 0)       atomicMin(&mins[0], t);
        if (raw >= Nc - 1)  atomicMin(&mins[1], t);
    }
    __syncthreads();
    if (t < 169) {
        int a = adj[t];
        unsigned char v = 1;
        if (a == 0      && t != mins[0]) v = 0;
        if (a == Nc - 1 && t != mins[1]) v = 0;
        vld[t] = v;
    }
    __syncthreads();

    const float* kvb = g_kv + (long)b * Nc * C2c;

    for (int h = 0; h < 8; h++) {
        float sv = -INFINITY;
        if (t < 169 && vld[t]) {
            const float4* kr = reinterpret_cast<const float4*>(
                kvb + (long)adj[t] * C2c + h * 48);
            const float4* qh = reinterpret_cast<const float4*>(qrow + h * 48);
            float d0 = 0.f;
#pragma unroll
            for (int j = 0; j < 12; j++) {
                float4 kq = kr[j], qq = qh[j];
                d0 += kq.x * qq.x + kq.y * qq.y + kq.z * qq.z + kq.w * qq.w;
            }
            sv = d0 * SCALE;
        }
        red[t] = sv;
        __syncthreads();
        for (int stp = 128; stp; stp >>= 1) {
            if (t < stp) red[t] = fmaxf(red[t], red[t + stp]);
            __syncthreads();
        }
        float mx = red[0];
        __syncthreads();
        float pv = 0.f;
        if (t < 169 && vld[t]) pv = expf(sv - mx);
        if (t < 169) sc[t] = pv;
        red[t] = pv;
        __syncthreads();
        for (int stp = 128; stp; stp >>= 1) {
            if (t < stp) red[t] += red[t + stp];
            __syncthreads();
        }
        float sm = red[0];
        __syncthreads();
        if (t < 192) {
            int g = t / 48, d = t % 48;
            float acc = 0.f;
            for (int i = g; i < 169; i += 4)
                acc += sc[i] * kvb[(long)adj[i] * C2c + 384 + h * 48 + d];
            pacc[t] = acc;
        }
        __syncthreads();
        if (t < 48) {
            float o = (pacc[t] + pacc[48 + t] + pacc[96 + t] + pacc[144 + t]) / sm;
            g_att[(long)bm * 384 + h * 48 + t] = o;
        }
        __syncthreads();
    }
}

// ---------------------------------------------------------------------------
// Host launch
// ---------------------------------------------------------------------------
static float* symf(const void* sym) {
    void* p = nullptr;
    cudaGetSymbolAddress(&p, sym);
    return (float*)p;
}

static void launch_gemm(const GP& p, int Z) {
    dim3 g((p.Nn + 63) / 64, (p.M + 63) / 64, Z);
    gemm_k<<<g, 256>>>(p);
}

extern "C" void kernel_launch(void* const* d_in, const int* in_sizes, int n_in,
                              void* d_out, int out_size) {
    (void)in_sizes; (void)n_in; (void)out_size;
    const float* x      = (const float*)d_in[0];
    const float* q      = (const float*)d_in[1];
    const float* kv_w   = (const float*)d_in[2];
    const float* proj_w = (const float*)d_in[3];
    const float* proj_b = (const float*)d_in[4];
    const float* ln_w   = (const float*)d_in[5];
    const float* ln_b   = (const float*)d_in[6];
    const float* fc1_w  = (const float*)d_in[7];
    const float* fc1_b  = (const float*)d_in[8];
    const float* fc2_w  = (const float*)d_in[9];
    const float* fc2_b  = (const float*)d_in[10];
    const int*   idx_sub= (const int*)d_in[11];
    const int*   idxs   = (const int*)d_in[12];
    float* out = (float*)d_out;

    float* p_xns   = symf(g_xns);
    float* p_xni   = symf(g_xni);
    float* p_kvsub = symf(g_kvsub);
    float* p_kidx  = symf(g_kidx);
    float* p_S     = symf(g_S);
    float* p_q1    = symf(g_q1);
    float* p_h     = symf(g_h);
    float* p_q2    = symf(g_q2);
    float* p_att   = symf(g_att);

    // 1. LN stats
    ln_stats_k<<<(Bc * Nc) / 4, 128>>>(x);

    // 2. KV GEMM via wmma tf32 (stage-3 consumer only)
    kv_wmma_k<<<dim3(C2c / 64, (Bc * Nc) / 128), 256>>>(x, kv_w, ln_w, ln_b);

    // 3. Exact fp32 path for gathered rows (argmax stability):
    gatherx_k<<<Bc * NTc, 128>>>(x, idx_sub, ln_w, ln_b, p_xns);
    gatherx_k<<<Bc * NTc, 128>>>(x, idxs,    ln_w, ln_b, p_xni);
    gemm128_k<false, false><<<dim3(C2c / 128, (Bc * NTc) / 128), 256>>>(
        p_xns, kv_w, p_kvsub, nullptr, C2c, Cc);
    gemm128_k<false, false><<<dim3(Cc / 128, (Bc * NTc) / 128), 256>>>(
        p_xni, kv_w, p_kidx, nullptr, Cc, Cc);

    // 4. attn1 scores
    {
        GP p = {};
        p.A = q; p.Bm = p_kvsub; p.Cm = p_S;
        p.sAm = 384; p.sAk = 1; p.strAb = 0;             p.strAh = 48;
        p.sBn = 768; p.sBk = 1; p.strBb = (long)NTc*768; p.strBh = 48;
        p.sCm = 196; p.sCn = 1; p.strCb = (long)8*196*196; p.strCh = (long)196*196;
        p.Hh = 8; p.M = 196; p.Nn = 196; p.K = 48; p.alpha = SCALE;
        launch_gemm(p, Bc * Hc);
    }

    // 5. softmax attn1
    softmax196_k<<<(Bc * Hc * NTc) / 4, 128>>>(p_S, Bc * Hc * NTc);

    // 6. P @ V
    {
        GP p = {};
        p.A = p_S; p.Bm = p_kvsub + 384; p.Cm = p_q1;
        p.sAm = 196; p.sAk = 1;   p.strAb = (long)8*196*196; p.strAh = (long)196*196;
        p.sBn = 1;   p.sBk = 768; p.strBb = (long)NTc*768;   p.strBh = 48;
        p.sCm = 384; p.sCn = 1;   p.strCb = (long)NTc*384;   p.strCh = 48;
        p.Hh = 8; p.M = 196; p.Nn = 48; p.K = 196; p.alpha = 1.f;
        launch_gemm(p, Bc * Hc);
    }

    // 7. fc1 + exact gelu
    gemm128_k<true, true><<<dim3(C2c / 128, (Bc * NTc) / 128), 256>>>(
        p_q1, fc1_w, p_h, fc1_b, C2c, Cc);

    // 8. fc2
    gemm128_k<true, false><<<dim3(Cc / 128, (Bc * NTc) / 128), 256>>>(
        p_h, fc2_w, p_q2, fc2_b, Cc, C2c);

    // 9. attn2 scores
    {
        GP p = {};
        p.A = p_q2; p.Bm = p_kidx; p.Cm = p_S;
        p.sAm = 384; p.sAk = 1; p.strAb = (long)NTc*384; p.strAh = 48;
        p.sBn = 384; p.sBk = 1; p.strBb = (long)NTc*384; p.strBh = 48;
        p.sCm = 196; p.sCn = 1; p.strCb = (long)8*196*196; p.strCh = (long)196*196;
        p.Hh = 8; p.M = 196; p.Nn = 196; p.K = 48; p.alpha = 1.f;
        launch_gemm(p, Bc * Hc);
    }

    // 10. centroids
    centroid_k<<<Bc * NTc, 256>>>(idxs);

    // 11. stage-3 windowed attention
    stage3_k<<<Bc * NTc, 256>>>();

    // 12. output projection
    gemm128_k<true, false><<<dim3(Cc / 128, (Bc * NTc) / 128), 256>>>(
        p_att, proj_w, out, proj_b, Cc, Cc);
}